// round 14
// baseline (speedup 1.0000x reference)
#include <cuda_runtime.h>
#include <cuda_fp16.h>
#include <math.h>

#define T_TOK 2048
#define H_DIM 2048
#define E_NUM 64
#define TOPK 6
#define F_DIM 768
#define G_NUM 8
#define GSZ 8
#define KG_NUM 4
#define CAP 384
#define SCALEF 2.5f

// GEMM tile config
#define BM 64
#define BN 64
#define BK 32
#define NTHREADS 256

// smem layout (element offsets, fp16) within ONE buffer
#define SA 40                     // A row stride
#define SB 72                     // B row stride
#define OFF_B     (BM * SA)               // 2560
#define BTILE     (BK * SB)               // 2304
#define BUFE_DUAL   (OFF_B + 2 * BTILE)   // 7168 elems
#define BUFE_SINGLE (OFF_B + 1 * BTILE)   // 4864 elems
#define SMEM_DUAL_BYTES   (2 * BUFE_DUAL * 2)     // 28672
#define SMEM_SINGLE_BYTES (2 * BUFE_SINGLE * 2)   // 19456

// ---------------- device scratch ----------------
__device__ int    g_cnt[E_NUM];
__device__ int    g_tok[E_NUM * CAP];
__device__ float  g_wt [E_NUM * CAP];
__device__ __half g_x16  [(size_t)T_TOK * H_DIM];
__device__ __half g_hbuf16[(size_t)E_NUM * CAP * F_DIM];
__device__ __half g_tmp16 [(size_t)T_TOK * F_DIM];

// ---------------- helpers ----------------
__device__ __forceinline__ void ldsm4(unsigned r[4], unsigned addr) {
    asm volatile("ldmatrix.sync.aligned.m8n8.x4.shared.b16 {%0,%1,%2,%3}, [%4];\n"
        : "=r"(r[0]), "=r"(r[1]), "=r"(r[2]), "=r"(r[3]) : "r"(addr));
}
__device__ __forceinline__ void ldsm4t(unsigned r[4], unsigned addr) {
    asm volatile("ldmatrix.sync.aligned.m8n8.x4.trans.shared.b16 {%0,%1,%2,%3}, [%4];\n"
        : "=r"(r[0]), "=r"(r[1]), "=r"(r[2]), "=r"(r[3]) : "r"(addr));
}
__device__ __forceinline__ void mma_f16(float c[4], const unsigned a[4],
                                        unsigned b0, unsigned b1) {
    asm volatile(
        "mma.sync.aligned.m16n8k16.row.col.f32.f16.f16.f32 "
        "{%0,%1,%2,%3},{%4,%5,%6,%7},{%8,%9},{%0,%1,%2,%3};\n"
        : "+f"(c[0]), "+f"(c[1]), "+f"(c[2]), "+f"(c[3])
        : "r"(a[0]), "r"(a[1]), "r"(a[2]), "r"(a[3]), "r"(b0), "r"(b1));
}
__device__ __forceinline__ void store_b(__half* dst, int off, float4 v) {
    union { __half b[4]; uint2 u; } H;
    H.b[0] = __float2half_rn(v.x);
    H.b[1] = __float2half_rn(v.y);
    H.b[2] = __float2half_rn(v.z);
    H.b[3] = __float2half_rn(v.w);
    *(uint2*)(dst + off) = H.u;
}

// ---------------- small kernels ----------------
__global__ void zero_cnt_kernel() {
    if (threadIdx.x < E_NUM) g_cnt[threadIdx.x] = 0;
}

__global__ void conv_x_kernel(const float* __restrict__ x) {
    int i = blockIdx.x * blockDim.x + threadIdx.x;
    float4 v = *(const float4*)(x + (size_t)i * 4);
    union { __half b[4]; uint2 u; } H;
    H.b[0] = __float2half_rn(v.x);
    H.b[1] = __float2half_rn(v.y);
    H.b[2] = __float2half_rn(v.z);
    H.b[3] = __float2half_rn(v.w);
    *(uint2*)(g_x16 + (size_t)i * 4) = H.u;
}

__global__ void router_kernel(const float* __restrict__ x,
                              const float* __restrict__ gw,
                              const float* __restrict__ bias) {
    int t = blockIdx.x;
    int tid = threadIdx.x;
    int e = tid & 63, part = tid >> 6;
    __shared__ float ps[4][E_NUM];
    __shared__ float sc[E_NUM];
    __shared__ float scb[E_NUM];

    const float* xr = x + (size_t)t * H_DIM;
    float acc = 0.f;
    int h0 = part * (H_DIM / 4);
    #pragma unroll 4
    for (int h = 0; h < H_DIM / 4; h++)
        acc += xr[h0 + h] * gw[(size_t)(h0 + h) * E_NUM + e];
    ps[part][e] = acc;
    __syncthreads();

    if (tid < E_NUM) {
        float l = ps[0][e] + ps[1][e] + ps[2][e] + ps[3][e];
        float s = 1.f / (1.f + __expf(-l));
        sc[e] = s;
        scb[e] = s + bias[e];
    }
    __syncthreads();

    if (tid == 0) {
        float gsc[G_NUM];
        for (int g = 0; g < G_NUM; g++) {
            float m1 = -1e30f, m2 = -1e30f;
            for (int i = 0; i < GSZ; i++) {
                float v = scb[g * GSZ + i];
                if (v > m1) { m2 = m1; m1 = v; }
                else if (v > m2) { m2 = v; }
            }
            gsc[g] = m1 + m2;
        }
        bool gsel[G_NUM];
        for (int g = 0; g < G_NUM; g++) gsel[g] = false;
        for (int r = 0; r < KG_NUM; r++) {
            int bi = -1; float bv = -1e30f;
            for (int g = 0; g < G_NUM; g++)
                if (!gsel[g] && gsc[g] > bv) { bv = gsc[g]; bi = g; }
            gsel[bi] = true;
        }
        bool esel[E_NUM];
        for (int i = 0; i < E_NUM; i++) esel[i] = false;
        int ids[TOPK]; float ws[TOPK]; float wsum = 0.f;
        for (int r = 0; r < TOPK; r++) {
            int bi = -1; float bv = -1e30f;
            for (int ee = 0; ee < E_NUM; ee++) {
                if (!gsel[ee / GSZ] || esel[ee]) continue;
                float v = scb[ee];
                if (v > bv) { bv = v; bi = ee; }
            }
            esel[bi] = true; ids[r] = bi; ws[r] = sc[bi]; wsum += sc[bi];
        }
        float inv = SCALEF / wsum;
        for (int r = 0; r < TOPK; r++) {
            int ee = ids[r];
            int slot = atomicAdd(&g_cnt[ee], 1);
            if (slot < CAP) {
                g_tok[ee * CAP + slot] = t;
                g_wt [ee * CAP + slot] = ws[r] * inv;
            }
        }
    }
}

// ---------------- tensor-core GEMM (fp16 x fp16, BM=64, 2-ahead prefetch) ----
// warp layout: 8 warps = 2 rows x 4 cols; warp tile 32m x 16n.
template<bool EXPERT, bool DUAL, int KDIM, int NDIM>
__global__ __launch_bounds__(NTHREADS, DUAL ? 2 : 3)
void mma_gemm(const __half* __restrict__ Abase,
              const float* __restrict__ W0base,
              const float* __restrict__ W1base,
              void* __restrict__ Cbase) {
    constexpr bool GATHER  = EXPERT && DUAL;
    constexpr bool SCATTER = EXPERT && !DUAL;
    constexpr int  BUFE    = DUAL ? BUFE_DUAL : BUFE_SINGLE;

    const int e = EXPERT ? blockIdx.z : 0;
    const int M = EXPERT ? min(g_cnt[e], CAP) : T_TOK;
    const int m0 = blockIdx.y * BM;
    if (m0 >= M) return;
    const int n0 = blockIdx.x * BN;

    const int* toks = EXPERT ? (g_tok + e * CAP) : nullptr;
    const __half* A = GATHER ? Abase
                             : (EXPERT ? Abase + (size_t)e * CAP * KDIM : Abase);
    const float* W0 = EXPERT ? W0base + (size_t)e * KDIM * NDIM : W0base;
    const float* W1 = nullptr;
    if (DUAL) W1 = EXPERT ? W1base + (size_t)e * KDIM * NDIM : W1base;
    __half* Ch = (DUAL && EXPERT)
                   ? ((__half*)Cbase + (size_t)e * CAP * NDIM)
                   : (__half*)Cbase;
    float*  Cf = (float*)Cbase;

    extern __shared__ char smem_raw[];
    __half* sm = (__half*)smem_raw;

    const int tid  = threadIdx.x;
    const int lane = tid & 31;
    const int wid  = tid >> 5;
    const int wm = wid & 1;     // 2 warp rows (32 m each)
    const int wn = wid >> 1;    // 4 warp cols (16 n each)

    // ----- staging assignments -----
    // A: 64 rows x 32 halves = 256 x 16B chunks -> 1 per thread
    const __half* aptr;
    int aoffs;
    {
        int row = tid >> 2;              // 0..63
        int c8  = (tid & 3) * 8;
        aoffs = row * SA + c8;
        int gr = m0 + row;
        if (GATHER) {
            int tk = (gr < M) ? toks[gr] : toks[0];
            aptr = A + (size_t)tk * KDIM + c8;
        } else {
            int r = (gr < M) ? gr : (M - 1);
            aptr = A + (size_t)r * KDIM + c8;
        }
    }
    // B: 32x64 fp32 = 512 float4 over 256 threads -> 2 each (per matrix)
    const float* bptr0[2];
    const float* bptr1[2];
    int boffs[2];
    #pragma unroll
    for (int i = 0; i < 2; i++) {
        int idx = tid + i * NTHREADS;
        int row = idx >> 4;              // 0..31
        int c4  = (idx & 15) * 4;
        boffs[i] = row * SB + c4;
        bptr0[i] = W0 + (size_t)row * NDIM + n0 + c4;
        if (DUAL) bptr1[i] = W1 + (size_t)row * NDIM + n0 + c4;
    }

    // ----- ldmatrix addresses (relative to buffer start) -----
    unsigned sbase = (unsigned)__cvta_generic_to_shared(smem_raw);
    const int ar  = lane & 15;
    const int ac8 = (lane >> 4) * 8;
    unsigned a_rel = ((wm * 32 + ar) * SA + ac8) * 2;
    unsigned b_rel = (OFF_B + (lane & 15) * SB + wn * 16 + ac8) * 2;

    float accg[2][2][4] = {};
    float accu[2][2][4] = {};

    // 2-slot prefetch registers (2 iterations ahead)
    uint4  avr[2];
    float4 bvr0[2][2], bvr1[2][2];

    // prologue: load tiles 0 and 1
    #pragma unroll
    for (int s = 0; s < 2; s++) {
        const int k = s * BK;
        avr[s] = *(const uint4*)(aptr + k);
        #pragma unroll
        for (int i = 0; i < 2; i++) {
            bvr0[s][i] = *(const float4*)(bptr0[i] + (size_t)k * NDIM);
            if (DUAL) bvr1[s][i] = *(const float4*)(bptr1[i] + (size_t)k * NDIM);
        }
    }

    constexpr int NIT = KDIM / BK;
    #pragma unroll 1
    for (int it = 0; it < NIT; it++) {
        const int slot = it & 1;
        const int bufo = slot ? BUFE : 0;
        __half* Ah = sm + bufo;
        __half* B0 = sm + bufo + OFF_B;
        __half* B1 = B0 + BTILE;

        // STS tile it from slot
        *(uint4*)(Ah + aoffs) = avr[slot];
        #pragma unroll
        for (int i = 0; i < 2; i++) {
            store_b(B0, boffs[i], bvr0[slot][i]);
            if (DUAL) store_b(B1, boffs[i], bvr1[slot][i]);
        }

        // LDG tile it+2 into the vacated slot
        if (it + 2 < NIT) {
            const int k = (it + 2) * BK;
            avr[slot] = *(const uint4*)(aptr + k);
            #pragma unroll
            for (int i = 0; i < 2; i++) {
                bvr0[slot][i] = *(const float4*)(bptr0[i] + (size_t)k * NDIM);
                if (DUAL) bvr1[slot][i] = *(const float4*)(bptr1[i] + (size_t)k * NDIM);
            }
        }
        __syncthreads();

        // compute on this buffer
        const unsigned a_addr = sbase + bufo * 2 + a_rel;
        const unsigned b_addr = sbase + bufo * 2 + b_rel;
        #pragma unroll
        for (int kk = 0; kk < BK; kk += 16) {
            unsigned ah[2][4];
            #pragma unroll
            for (int mi = 0; mi < 2; mi++)
                ldsm4(ah[mi], a_addr + (mi * 16 * SA + kk) * 2);
            {
                unsigned bh[4];
                ldsm4t(bh, b_addr + (kk * SB) * 2);
                #pragma unroll
                for (int mi = 0; mi < 2; mi++)
                    #pragma unroll
                    for (int s = 0; s < 2; s++)
                        mma_f16(accg[mi][s], ah[mi], bh[2 * s], bh[2 * s + 1]);
            }
            if (DUAL) {
                unsigned bh[4];
                ldsm4t(bh, b_addr + (BTILE + kk * SB) * 2);
                #pragma unroll
                for (int mi = 0; mi < 2; mi++)
                    #pragma unroll
                    for (int s = 0; s < 2; s++)
                        mma_f16(accu[mi][s], ah[mi], bh[2 * s], bh[2 * s + 1]);
            }
        }
    }

    // ----- epilogue -----
    const int g  = lane >> 2;
    const int t4 = lane & 3;
    #pragma unroll
    for (int mi = 0; mi < 2; mi++) {
        #pragma unroll
        for (int nc = 0; nc < 2; nc++) {
            int col = n0 + wn * 16 + nc * 8 + t4 * 2;
            #pragma unroll
            for (int h = 0; h < 2; h++) {
                int m = m0 + wm * 32 + mi * 16 + g + h * 8;
                if (m >= M) continue;
                float c0 = accg[mi][nc][h * 2];
                float c1 = accg[mi][nc][h * 2 + 1];
                if (DUAL) {
                    float u0 = accu[mi][nc][h * 2];
                    float u1 = accu[mi][nc][h * 2 + 1];
                    float v0 = c0 / (1.f + __expf(-c0)) * u0;
                    float v1 = c1 / (1.f + __expf(-c1)) * u1;
                    __half2 o = __floats2half2_rn(v0, v1);
                    *(__half2*)(Ch + (size_t)m * NDIM + col) = o;
                } else if (SCATTER) {
                    float w = g_wt[e * CAP + m];
                    float* o = Cf + (size_t)toks[m] * NDIM + col;
                    atomicAdd(o, c0 * w);
                    atomicAdd(o + 1, c1 * w);
                } else {
                    *(float2*)(Cf + (size_t)m * NDIM + col) = make_float2(c0, c1);
                }
            }
        }
    }
}

// ---------------- launch ----------------
extern "C" void kernel_launch(void* const* d_in, const int* in_sizes, int n_in,
                              void* d_out, int out_size) {
    const float* x       = (const float*)d_in[0];
    const float* gate_w  = (const float*)d_in[1];
    const float* bias    = (const float*)d_in[2];
    const float* w_gate  = (const float*)d_in[3];
    const float* w_up    = (const float*)d_in[4];
    const float* w_down  = (const float*)d_in[5];
    const float* ws_gate = (const float*)d_in[6];
    const float* ws_up   = (const float*)d_in[7];
    const float* ws_down = (const float*)d_in[8];
    float* out = (float*)d_out;

    __half* x16;  cudaGetSymbolAddress((void**)&x16,  g_x16);
    __half* hbuf; cudaGetSymbolAddress((void**)&hbuf, g_hbuf16);
    __half* tmp;  cudaGetSymbolAddress((void**)&tmp,  g_tmp16);

    cudaFuncSetAttribute(mma_gemm<false, true,  H_DIM, F_DIM>,
                         cudaFuncAttributeMaxDynamicSharedMemorySize, SMEM_DUAL_BYTES);
    cudaFuncSetAttribute(mma_gemm<false, false, F_DIM, H_DIM>,
                         cudaFuncAttributeMaxDynamicSharedMemorySize, SMEM_SINGLE_BYTES);
    cudaFuncSetAttribute(mma_gemm<true,  true,  H_DIM, F_DIM>,
                         cudaFuncAttributeMaxDynamicSharedMemorySize, SMEM_DUAL_BYTES);
    cudaFuncSetAttribute(mma_gemm<true,  false, F_DIM, H_DIM>,
                         cudaFuncAttributeMaxDynamicSharedMemorySize, SMEM_SINGLE_BYTES);

    zero_cnt_kernel<<<1, 64>>>();
    conv_x_kernel<<<(T_TOK * H_DIM / 4) / 256, 256>>>(x);
    router_kernel<<<T_TOK, 256>>>(x, gate_w, bias);

    // shared expert (plain stores initialize d_out)
    mma_gemm<false, true, H_DIM, F_DIM>
        <<<dim3(F_DIM / BN, T_TOK / BM, 1), NTHREADS, SMEM_DUAL_BYTES>>>(
            x16, ws_gate, ws_up, tmp);
    mma_gemm<false, false, F_DIM, H_DIM>
        <<<dim3(H_DIM / BN, T_TOK / BM, 1), NTHREADS, SMEM_SINGLE_BYTES>>>(
            tmp, ws_down, nullptr, out);

    // routed experts
    mma_gemm<true, true, H_DIM, F_DIM>
        <<<dim3(F_DIM / BN, CAP / BM, E_NUM), NTHREADS, SMEM_DUAL_BYTES>>>(
            x16, w_gate, w_up, hbuf);
    mma_gemm<true, false, F_DIM, H_DIM>
        <<<dim3(H_DIM / BN, CAP / BM, E_NUM), NTHREADS, SMEM_SINGLE_BYTES>>>(
            hbuf, w_down, nullptr, out);
}